// round 16
// baseline (speedup 1.0000x reference)
#include <cuda_runtime.h>
#include <cuda_fp16.h>
#include <cstdint>

#define NN 50000
#define EE 800000
#define FF 128
#define KK 8
#define DD 16
#define GG 512
#define GC 3
#define BN_EPS 1e-5f
#define NB 196   // ceil(NN/256)

// ---------------- static scratch ----------------
__device__ float    d_z[NN * FF];
__device__ __half   d_hh[NN * FF];     // fp16 bn(z) for gather
__device__ uint32_t d_aggH[NN * 64];   // packed bf16-hi pairs of agg
__device__ uint32_t d_aggL[NN * 64];
__device__ uint32_t d_WF32[8 * 16384]; // interleaved frags: {H0,H1,L0,L1} per (n,ks,j)
__device__ int      d_deg[NN];
__device__ int      d_rowptr[NN];
__device__ int      d_cur[NN];
__device__ int      d_esrc[EE];
__device__ int      d_bsumblk[256];
__device__ int      d_gcnt[GG];
__device__ float    d_bsumL[5 * FF];
__device__ float    d_bsqL[5 * FF];
__device__ float    d_bcat[FF];
__device__ float    d_bcat2[FF];

// ================= helpers =================
__device__ __forceinline__ uint32_t smem_u32(const void* p) {
    uint32_t a;
    asm("{ .reg .u64 t; cvta.to.shared.u64 t, %1; cvt.u32.u64 %0, t; }" : "=r"(a) : "l"(p));
    return a;
}
__device__ __forceinline__ uint32_t h2_to_u(__half2 h) {
    return *reinterpret_cast<uint32_t*>(&h);
}
__device__ __forceinline__ float2 u_to_f2(uint32_t u) {
    __half2 h = *reinterpret_cast<__half2*>(&u);
    return __half22float2(h);
}
__device__ __forceinline__ void split1(float v, uint32_t& h, uint32_t& l) {
    uint32_t u = __float_as_uint(v);
    uint32_t hr = (u + 0x7FFFu + ((u >> 16) & 1u)) & 0xFFFF0000u;
    float hf = __uint_as_float(hr);
    float lf = v - hf;
    uint32_t ul = __float_as_uint(lf);
    h = hr >> 16;
    l = (ul + 0x7FFFu + ((ul >> 16) & 1u)) >> 16;
}
__device__ __forceinline__ void unpack2(uint32_t h, uint32_t l, float& a, float& b) {
    a = __uint_as_float((h & 0xFFFFu) << 16) + __uint_as_float((l & 0xFFFFu) << 16);
    b = __uint_as_float(h & 0xFFFF0000u) + __uint_as_float(l & 0xFFFF0000u);
}
__device__ __forceinline__ void ldsm4(uint32_t* r, uint32_t addr) {
    asm volatile("ldmatrix.sync.aligned.m8n8.x4.shared.b16 {%0,%1,%2,%3}, [%4];"
                 : "=r"(r[0]), "=r"(r[1]), "=r"(r[2]), "=r"(r[3]) : "r"(addr));
}
__device__ __forceinline__ void mma_bf16(float* c, const uint32_t* a, const uint32_t* b) {
    asm volatile(
        "mma.sync.aligned.m16n8k16.row.col.f32.bf16.bf16.f32 "
        "{%0,%1,%2,%3}, {%4,%5,%6,%7}, {%8,%9}, {%0,%1,%2,%3};"
        : "+f"(c[0]), "+f"(c[1]), "+f"(c[2]), "+f"(c[3])
        : "r"(a[0]), "r"(a[1]), "r"(a[2]), "r"(a[3]), "r"(b[0]), "r"(b[1]));
}
__device__ __forceinline__ void add8(float* acc, uint4 v) {
    float2 p0 = u_to_f2(v.x), p1 = u_to_f2(v.y), p2 = u_to_f2(v.z), p3 = u_to_f2(v.w);
    acc[0] += p0.x; acc[1] += p0.y; acc[2] += p1.x; acc[3] += p1.y;
    acc[4] += p2.x; acc[5] += p2.y; acc[6] += p3.x; acc[7] += p3.y;
}

#define RSTRIDE 272
#define O_AH 0
#define O_AL 34816
#define SM_G 69632

// ---------------- prep0: zero + weights + hist + x->fp16, all independent ----------------
__global__ void __launch_bounds__(256) prep0_kernel(const float* __restrict__ gc_W1,
                                                    const float* __restrict__ gc_W2,
                                                    const float* __restrict__ h0_W1,
                                                    const float* __restrict__ h0_b1,
                                                    const float* __restrict__ h0_W2,
                                                    const float* __restrict__ h0_b2,
                                                    const float* __restrict__ x,
                                                    const int* __restrict__ dst,
                                                    const int* __restrict__ batch,
                                                    float* __restrict__ out) {
    int idx = blockIdx.x * 256 + threadIdx.x;   // 800000 threads

    if (idx < EE) atomicAdd(&d_deg[dst[idx]], 1);
    if (idx < NN) atomicAdd(&d_gcnt[batch[idx]], 1);

    if (idx < GG * FF) out[idx] = 0.f;
    if (idx < 5 * FF) { d_bsumL[idx] = 0.f; d_bsqL[idx] = 0.f; }
    if (idx < FF) {
        d_bcat[idx]  = h0_b1[(idx >> 4) * DD + (idx & 15)];
        d_bcat2[idx] = h0_b2[(idx >> 4) * DD + (idx & 15)];
    }

    // weight conversion -> interleaved fragment layout
    // o = ((n*8+ks)*4+j)*2 + which; q = o>>1; WF[s*16384 + q*4 + which] = H; +2 = L
    if (idx < 8 * 8192) {
        int s = idx >> 13, o = idx & 8191;
        int which = o & 1, j = (o >> 1) & 3, ks = (o >> 3) & 7, n = o >> 6;
        int kp = ks * 8 + j + which * 4;
        int k0 = kp * 2, k1 = k0 + 1;
        float w0, w1;
        if (s < 6) {
            const float* W = ((s & 1) ? gc_W2 : gc_W1) + (s >> 1) * 16384;
            w0 = W[k0 * 128 + n];
            w1 = W[k1 * 128 + n];
        } else if (s == 6) {
            w0 = h0_W1[(n >> 4) * (FF * DD) + k0 * DD + (n & 15)];
            w1 = h0_W1[(n >> 4) * (FF * DD) + k1 * DD + (n & 15)];
        } else {
            int kb = n >> 4;
            w0 = ((k0 >> 4) == kb) ? h0_W2[kb * (DD * DD) + (k0 & 15) * DD + (n & 15)] : 0.f;
            w1 = ((k1 >> 4) == kb) ? h0_W2[kb * (DD * DD) + (k1 & 15) * DD + (n & 15)] : 0.f;
        }
        uint32_t h0v, l0, h1v, l1;
        split1(w0, h0v, l0); split1(w1, h1v, l1);
        int q = o >> 1;
        d_WF32[s * 16384 + q * 4 + which]     = h0v | (h1v << 16);
        d_WF32[s * 16384 + q * 4 + 2 + which] = l0 | (l1 << 16);
    }

    if (idx < NN * 16) {
        int f8 = (idx & 15) << 3;
        const float4* zp = (const float4*)(x + ((size_t)(idx >> 4) << 7) + f8);
        float4 v0 = zp[0], v1 = zp[1];
        uint4 o2;
        o2.x = h2_to_u(__floats2half2_rn(v0.x, v0.y));
        o2.y = h2_to_u(__floats2half2_rn(v0.z, v0.w));
        o2.z = h2_to_u(__floats2half2_rn(v1.x, v1.y));
        o2.w = h2_to_u(__floats2half2_rn(v1.z, v1.w));
        *(uint4*)(d_hh + ((size_t)(idx >> 4) << 7) + f8) = o2;
    }
}

__global__ void zero_deg_kernel() {
    int n = blockIdx.x * 256 + threadIdx.x;
    if (n < NN) d_deg[n] = 0;
    if (n < GG) d_gcnt[n] = 0;
}

__global__ void scan1_kernel() {
    __shared__ int s[256];
    int n = blockIdx.x * 256 + threadIdx.x;
    s[threadIdx.x] = (n < NN) ? d_deg[n] : 0;
    __syncthreads();
    for (int o = 128; o > 0; o >>= 1) {
        if (threadIdx.x < o) s[threadIdx.x] += s[threadIdx.x + o];
        __syncthreads();
    }
    if (threadIdx.x == 0) d_bsumblk[blockIdx.x] = s[0];
}
__global__ void scan23_kernel() {
    __shared__ int sb[256];
    __shared__ int s[256];
    int tid = threadIdx.x;
    int bv = (tid < NB) ? d_bsumblk[tid] : 0;
    sb[tid] = bv;
    __syncthreads();
    for (int o = 1; o < 256; o <<= 1) {
        int t = (tid >= o) ? sb[tid - o] : 0;
        __syncthreads();
        sb[tid] += t;
        __syncthreads();
    }
    int block_off = sb[blockIdx.x] - ((blockIdx.x < NB) ? d_bsumblk[blockIdx.x] : 0);
    __syncthreads();
    int n = blockIdx.x * 256 + tid;
    int v = (n < NN) ? d_deg[n] : 0;
    s[tid] = v;
    __syncthreads();
    for (int o = 1; o < 256; o <<= 1) {
        int t = (tid >= o) ? s[tid - o] : 0;
        __syncthreads();
        s[tid] += t;
        __syncthreads();
    }
    if (n < NN) {
        int rp = block_off + s[tid] - v;
        d_rowptr[n] = rp;
        d_cur[n] = rp;
    }
}
__global__ void fill_kernel(const int* __restrict__ src, const int* __restrict__ dst) {
    int e = blockIdx.x * 256 + threadIdx.x;
    if (e >= EE) return;
    int pos = atomicAdd(&d_cur[dst[e]], 1);
    d_esrc[pos] = src[e];
}

// ---------------- bnh: d_hh = half(bn(z)(+relu)) ----------------
__global__ void __launch_bounds__(256) bnh_kernel(const float* __restrict__ z,
                                                  const float* __restrict__ g,
                                                  const float* __restrict__ be,
                                                  const float* __restrict__ bsum,
                                                  const float* __restrict__ bsq,
                                                  int relu) {
    __shared__ float ssc[FF], ssh[FF];
    int tid = threadIdx.x;
    if (tid < FF) {
        float mu  = bsum[tid] * (1.0f / NN);
        float var = bsq[tid]  * (1.0f / NN) - mu * mu;
        float sc  = g[tid] * rsqrtf(var + BN_EPS);
        ssc[tid] = sc;
        ssh[tid] = be[tid] - mu * sc;
    }
    __syncthreads();
    int idx = blockIdx.x * 256 + tid;
    if (idx >= NN * 16) return;
    int f8 = (idx & 15) << 3;
    const float4* zp = (const float4*)(z + ((size_t)(idx >> 4) << 7) + f8);
    float4 v0 = zp[0], v1 = zp[1];
    float4 sc0 = *(const float4*)&ssc[f8], sh0 = *(const float4*)&ssh[f8];
    float4 sc1 = *(const float4*)&ssc[f8 + 4], sh1 = *(const float4*)&ssh[f8 + 4];
    v0.x = v0.x * sc0.x + sh0.x; v0.y = v0.y * sc0.y + sh0.y;
    v0.z = v0.z * sc0.z + sh0.z; v0.w = v0.w * sc0.w + sh0.w;
    v1.x = v1.x * sc1.x + sh1.x; v1.y = v1.y * sc1.y + sh1.y;
    v1.z = v1.z * sc1.z + sh1.z; v1.w = v1.w * sc1.w + sh1.w;
    if (relu) {
        v0.x = fmaxf(v0.x, 0.f); v0.y = fmaxf(v0.y, 0.f);
        v0.z = fmaxf(v0.z, 0.f); v0.w = fmaxf(v0.w, 0.f);
        v1.x = fmaxf(v1.x, 0.f); v1.y = fmaxf(v1.y, 0.f);
        v1.z = fmaxf(v1.z, 0.f); v1.w = fmaxf(v1.w, 0.f);
    }
    uint4 o;
    o.x = h2_to_u(__floats2half2_rn(v0.x, v0.y));
    o.y = h2_to_u(__floats2half2_rn(v0.z, v0.w));
    o.z = h2_to_u(__floats2half2_rn(v1.x, v1.y));
    o.w = h2_to_u(__floats2half2_rn(v1.z, v1.w));
    *(uint4*)(d_hh + ((size_t)(idx >> 4) << 7) + f8) = o;
}

// ---------------- gather: warp/node, 4 edges in flight per lane-half ----------------
__global__ void __launch_bounds__(256) gather_kernel() {
    int gt = blockIdx.x * 256 + threadIdx.x;
    int w = gt >> 5, lane = gt & 31;
    if (w >= NN) return;
    int half = lane >> 4;
    int fo = (lane & 15) << 3;
    int start = d_rowptr[w];
    int deg = d_deg[w];

    float acc[8];
#pragma unroll
    for (int j = 0; j < 8; j++) acc[j] = 0.f;

    if (half == 0)
        add8(acc, *(const uint4*)(d_hh + ((size_t)w << 7) + fo));

    int i = half;
    for (; i + 6 < deg; i += 8) {
        int s0 = d_esrc[start + i];
        int s1 = d_esrc[start + i + 2];
        int s2 = d_esrc[start + i + 4];
        int s3 = d_esrc[start + i + 6];
        uint4 v0 = *(const uint4*)(d_hh + ((size_t)s0 << 7) + fo);
        uint4 v1 = *(const uint4*)(d_hh + ((size_t)s1 << 7) + fo);
        uint4 v2 = *(const uint4*)(d_hh + ((size_t)s2 << 7) + fo);
        uint4 v3 = *(const uint4*)(d_hh + ((size_t)s3 << 7) + fo);
        add8(acc, v0);
        add8(acc, v1);
        add8(acc, v2);
        add8(acc, v3);
    }
    for (; i < deg; i += 2) {
        int s0 = d_esrc[start + i];
        add8(acc, *(const uint4*)(d_hh + ((size_t)s0 << 7) + fo));
    }

#pragma unroll
    for (int j = 0; j < 8; j++)
        acc[j] += __shfl_xor_sync(0xFFFFFFFFu, acc[j], 16);

    if (half == 0) {
        uint32_t ph[4], pl[4];
#pragma unroll
        for (int j = 0; j < 4; j++) {
            uint32_t h0, l0, h1, l1;
            split1(acc[2 * j], h0, l0);
            split1(acc[2 * j + 1], h1, l1);
            ph[j] = h0 | (h1 << 16);
            pl[j] = l0 | (l1 << 16);
        }
        size_t base = (size_t)w * 64 + ((lane & 15) << 2);
        *(uint4*)&d_aggH[base] = make_uint4(ph[0], ph[1], ph[2], ph[3]);
        *(uint4*)&d_aggL[base] = make_uint4(pl[0], pl[1], pl[2], pl[3]);
    }
}

// ---------------- fused double GEMM: z = relu(A@W1+b1)@W2 + b2 (+stats) ----------------
// W fragments interleaved {H0,H1,L0,L1}: one LDG.128 per (nt,ks) per thread.
__global__ void __launch_bounds__(256, 2) fgemm_kernel(const uint32_t* __restrict__ AH,
                                                       const uint32_t* __restrict__ AL,
                                                       const uint32_t* __restrict__ W1F,
                                                       const float* __restrict__ b1,
                                                       const uint32_t* __restrict__ W2F,
                                                       const float* __restrict__ b2,
                                                       float* __restrict__ Cz,
                                                       float* __restrict__ bsum,
                                                       float* __restrict__ bsq,
                                                       int M) {
    extern __shared__ char sm[];
    uint32_t sb = smem_u32(sm);
    const int tid = threadIdx.x;
    const int row0 = blockIdx.x * 128;

    for (int i = tid; i < 2048; i += 256) {
        int m = i >> 4, c4 = (i & 15) << 2;
        int r = row0 + m; if (r >= M) r = M - 1;
        uint32_t off = (uint32_t)m * RSTRIDE + (c4 << 2);
        *(uint4*)(sm + O_AH + off) = *(const uint4*)&AH[(size_t)r * 64 + c4];
        *(uint4*)(sm + O_AL + off) = *(const uint4*)&AL[(size_t)r * 64 + c4];
    }
    __syncthreads();

    const int wid = tid >> 5, lane = tid & 31;
    const int mw = (wid & 1) << 6;
    const int nw = (wid >> 1) << 5;
    const int lane15 = lane & 15, lhi = lane >> 4;
    const int rr = lane >> 2, cc = (lane & 3) << 1;

    uint32_t baseA = sb + O_AH + (uint32_t)(mw + lane15) * RSTRIDE + (lhi << 4);
    // fi4 = n*128 + ks*16 + j*4 ; n = nw + nt*8 + (lane>>2), j = lane&3
    const uint32_t fb4 = (uint32_t)(nw + (lane >> 2)) * 128 + ((lane & 3) << 2);

    float c[4][4][4];

#define MMA_PHASE(WF_)                                                           \
    _Pragma("unroll 2")                                                          \
    for (int ks = 0; ks < 8; ks++) {                                             \
        uint32_t ah[4][4], al[4][4];                                             \
        _Pragma("unroll")                                                        \
        for (int mt = 0; mt < 4; mt++) {                                         \
            uint32_t ad = baseA + mt * (16 * RSTRIDE) + ks * 32;                 \
            ldsm4(ah[mt], ad);                                                   \
            ldsm4(al[mt], ad + (O_AL - O_AH));                                   \
        }                                                                        \
        uint32_t bh[4][2], bl[4][2];                                             \
        _Pragma("unroll")                                                        \
        for (int nt = 0; nt < 4; nt++) {                                         \
            uint32_t fi4 = fb4 + (uint32_t)nt * 1024 + (uint32_t)ks * 16;        \
            uint4 vf = *(const uint4*)&WF_[fi4];                                 \
            bh[nt][0] = vf.x; bh[nt][1] = vf.y;                                  \
            bl[nt][0] = vf.z; bl[nt][1] = vf.w;                                  \
        }                                                                        \
        _Pragma("unroll")                                                        \
        for (int mt = 0; mt < 4; mt++)                                           \
            _Pragma("unroll")                                                    \
            for (int nt = 0; nt < 4; nt++) {                                     \
                mma_bf16(c[mt][nt], ah[mt], bh[nt]);                             \
                mma_bf16(c[mt][nt], ah[mt], bl[nt]);                             \
                mma_bf16(c[mt][nt], al[mt], bh[nt]);                             \
            }                                                                    \
    }

    // ---- phase 1: t = relu(A@W1 + b1) ----
#pragma unroll
    for (int a = 0; a < 4; a++)
#pragma unroll
        for (int b = 0; b < 4; b++)
#pragma unroll
            for (int d = 0; d < 4; d++) c[a][b][d] = 0.f;
    MMA_PHASE(W1F);
    __syncthreads();

#pragma unroll
    for (int mt = 0; mt < 4; mt++) {
        int mr0 = mw + mt * 16 + rr;
        int mr1 = mr0 + 8;
#pragma unroll
        for (int nt = 0; nt < 4; nt++) {
            int gc = nw + nt * 8 + cc;
            float bx = b1[gc], by = b1[gc + 1];
            float v0 = fmaxf(c[mt][nt][0] + bx, 0.f);
            float v1 = fmaxf(c[mt][nt][1] + by, 0.f);
            float v2 = fmaxf(c[mt][nt][2] + bx, 0.f);
            float v3 = fmaxf(c[mt][nt][3] + by, 0.f);
            uint32_t h0, l0, h1, l1, h2, l2, h3, l3;
            split1(v0, h0, l0); split1(v1, h1, l1);
            split1(v2, h2, l2); split1(v3, h3, l3);
            uint32_t off0 = (uint32_t)mr0 * RSTRIDE + ((gc >> 1) << 2);
            uint32_t off1 = (uint32_t)mr1 * RSTRIDE + ((gc >> 1) << 2);
            *(uint32_t*)(sm + O_AH + off0) = h0 | (h1 << 16);
            *(uint32_t*)(sm + O_AL + off0) = l0 | (l1 << 16);
            *(uint32_t*)(sm + O_AH + off1) = h2 | (h3 << 16);
            *(uint32_t*)(sm + O_AL + off1) = l2 | (l3 << 16);
        }
    }
    __syncthreads();

    // ---- phase 2: z = t@W2 + b2 ----
#pragma unroll
    for (int a = 0; a < 4; a++)
#pragma unroll
        for (int b = 0; b < 4; b++)
#pragma unroll
            for (int d = 0; d < 4; d++) c[a][b][d] = 0.f;
    MMA_PHASE(W2F);

    float s[4][2], q[4][2];
#pragma unroll
    for (int nt = 0; nt < 4; nt++) { s[nt][0] = s[nt][1] = q[nt][0] = q[nt][1] = 0.f; }
#pragma unroll
    for (int mt = 0; mt < 4; mt++) {
        int gr0 = row0 + mw + mt * 16 + rr;
        int gr1 = gr0 + 8;
#pragma unroll
        for (int nt = 0; nt < 4; nt++) {
            int gc = nw + nt * 8 + cc;
            float bx = b2[gc], by = b2[gc + 1];
            float v0 = c[mt][nt][0] + bx, v1 = c[mt][nt][1] + by;
            float v2 = c[mt][nt][2] + bx, v3 = c[mt][nt][3] + by;
            if (gr0 < M) {
                *(float2*)(Cz + (size_t)gr0 * FF + gc) = make_float2(v0, v1);
                s[nt][0] += v0; q[nt][0] += v0 * v0; s[nt][1] += v1; q[nt][1] += v1 * v1;
            }
            if (gr1 < M) {
                *(float2*)(Cz + (size_t)gr1 * FF + gc) = make_float2(v2, v3);
                s[nt][0] += v2; q[nt][0] += v2 * v2; s[nt][1] += v3; q[nt][1] += v3 * v3;
            }
        }
    }
#pragma unroll
    for (int off = 16; off >= 4; off >>= 1) {
#pragma unroll
        for (int nt = 0; nt < 4; nt++) {
#pragma unroll
            for (int j = 0; j < 2; j++) {
                s[nt][j] += __shfl_xor_sync(0xFFFFFFFFu, s[nt][j], off);
                q[nt][j] += __shfl_xor_sync(0xFFFFFFFFu, q[nt][j], off);
            }
        }
    }
    if (lane < 4) {
#pragma unroll
        for (int nt = 0; nt < 4; nt++) {
            int gc = nw + nt * 8 + (lane << 1);
            atomicAdd(&bsum[gc], s[nt][0]);
            atomicAdd(&bsum[gc + 1], s[nt][1]);
            atomicAdd(&bsq[gc], q[nt][0]);
            atomicAdd(&bsq[gc + 1], q[nt][1]);
        }
    }
#undef MMA_PHASE
}

// ---------------- block-diag double + fused stats + direct raw pooling ----------------
__global__ void __launch_bounds__(256) bdiag2_pool_kernel(const uint32_t* __restrict__ XH,
                                                          const uint32_t* __restrict__ XL,
                                                          const float* __restrict__ W1,
                                                          const float* __restrict__ B1,
                                                          const float* __restrict__ W2,
                                                          const float* __restrict__ B2,
                                                          const int* __restrict__ batch,
                                                          float* __restrict__ out,
                                                          float* __restrict__ bsum,
                                                          float* __restrict__ bsq) {
    __shared__ float sW1[8 * 257];
    __shared__ float sW2[8 * 257];
    __shared__ float sB1[128];
    __shared__ float sB2[128];
    __shared__ float sSum[128], sSq[128];
    int tid = threadIdx.x;
    for (int i = tid; i < 2048; i += 256) {
        sW1[(i >> 8) * 257 + (i & 255)] = W1[i];
        sW2[(i >> 8) * 257 + (i & 255)] = W2[i];
    }
    if (tid < 128) { sB1[tid] = B1[tid]; sB2[tid] = B2[tid]; sSum[tid] = 0.f; sSq[tid] = 0.f; }
    __syncthreads();
    int k = tid & 7;
    const float* w1 = sW1 + k * 257;
    const float* w2 = sW2 + k * 257;
    float s[16], q[16];
#pragma unroll
    for (int j = 0; j < 16; j++) { s[j] = 0.f; q[j] = 0.f; }

    for (int it = 0; it < 4; it++) {
        int n = blockIdx.x * 128 + it * 32 + (tid >> 3);
        if (n >= NN) break;
        size_t base = (size_t)n * 64 + k * 8;
        uint4 vh0 = *(const uint4*)&XH[base];
        uint4 vh1 = *(const uint4*)&XH[base + 4];
        uint4 vl0 = *(const uint4*)&XL[base];
        uint4 vl1 = *(const uint4*)&XL[base + 4];
        float x[16];
        unpack2(vh0.x, vl0.x, x[0], x[1]);   unpack2(vh0.y, vl0.y, x[2], x[3]);
        unpack2(vh0.z, vl0.z, x[4], x[5]);   unpack2(vh0.w, vl0.w, x[6], x[7]);
        unpack2(vh1.x, vl1.x, x[8], x[9]);   unpack2(vh1.y, vl1.y, x[10], x[11]);
        unpack2(vh1.z, vl1.z, x[12], x[13]); unpack2(vh1.w, vl1.w, x[14], x[15]);
        float t[16];
#pragma unroll
        for (int j = 0; j < 16; j++) t[j] = sB1[k * 16 + j];
#pragma unroll
        for (int i2 = 0; i2 < 16; i2++) {
            float xi = x[i2];
#pragma unroll
            for (int j = 0; j < 16; j++) t[j] += xi * w1[i2 * 16 + j];
        }
#pragma unroll
        for (int j = 0; j < 16; j++) t[j] = fmaxf(t[j], 0.f);
        float o[16];
#pragma unroll
        for (int j = 0; j < 16; j++) o[j] = sB2[k * 16 + j];
#pragma unroll
        for (int i2 = 0; i2 < 16; i2++) {
            float ti = t[i2];
#pragma unroll
            for (int j = 0; j < 16; j++) o[j] += ti * w2[i2 * 16 + j];
        }
        int g = batch[n];
        float* op = out + (size_t)g * FF + k * DD;
#pragma unroll
        for (int i2 = 0; i2 < 4; i2++) {
            asm volatile("red.global.add.v4.f32 [%0], {%1,%2,%3,%4};"
                         :: "l"(op + 4 * i2), "f"(o[4*i2]), "f"(o[4*i2+1]),
                            "f"(o[4*i2+2]), "f"(o[4*i2+3]) : "memory");
        }
#pragma unroll
        for (int j = 0; j < 16; j++) { s[j] += o[j]; q[j] += o[j] * o[j]; }
    }
#pragma unroll
    for (int off = 16; off >= 8; off >>= 1) {
#pragma unroll
        for (int j = 0; j < 16; j++) {
            s[j] += __shfl_xor_sync(0xFFFFFFFFu, s[j], off);
            q[j] += __shfl_xor_sync(0xFFFFFFFFu, q[j], off);
        }
    }
    if ((tid & 31) < 8) {
#pragma unroll
        for (int j = 0; j < 16; j++) {
            atomicAdd(&sSum[k * 16 + j], s[j]);
            atomicAdd(&sSq[k * 16 + j], q[j]);
        }
    }
    __syncthreads();
    if (tid < 128) {
        atomicAdd(&bsum[tid], sSum[tid]);
        atomicAdd(&bsq[tid], sSq[tid]);
    }
}

// ---------------- finalize: out = out*sc + cnt_g*sh ----------------
__global__ void __launch_bounds__(256) finalize_kernel(float* __restrict__ out,
                                                       const float* __restrict__ g,
                                                       const float* __restrict__ be,
                                                       const float* __restrict__ bsum,
                                                       const float* __restrict__ bsq) {
    int idx = blockIdx.x * 256 + threadIdx.x;
    if (idx >= GG * FF) return;
    int f = idx & 127;
    int gi = idx >> 7;
    float mu  = bsum[f] * (1.0f / NN);
    float var = bsq[f]  * (1.0f / NN) - mu * mu;
    float sc  = g[f] * rsqrtf(var + BN_EPS);
    float sh  = be[f] - mu * sc;
    out[idx] = out[idx] * sc + (float)d_gcnt[gi] * sh;
}

// ---------------- host orchestration ----------------
extern "C" void kernel_launch(void* const* d_in, const int* in_sizes, int n_in,
                              void* d_out, int out_size) {
    const float* x     = (const float*)d_in[0];
    const int*   ei    = (const int*)d_in[1];
    const int*   batch = (const int*)d_in[2];
    const float* gc_W1 = (const float*)d_in[4];
    const float* gc_b1 = (const float*)d_in[5];
    const float* gc_W2 = (const float*)d_in[6];
    const float* gc_b2 = (const float*)d_in[7];
    const float* gc_g  = (const float*)d_in[8];
    const float* gc_be = (const float*)d_in[9];
    const float* h0_W1 = (const float*)d_in[10];
    const float* h0_b1 = (const float*)d_in[11];
    const float* h0_W2 = (const float*)d_in[12];
    const float* h0_b2 = (const float*)d_in[13];
    const float* h0_g  = (const float*)d_in[14];
    const float* h0_be = (const float*)d_in[15];
    const float* h1_W1 = (const float*)d_in[16];
    const float* h1_b1 = (const float*)d_in[17];
    const float* h1_W2 = (const float*)d_in[18];
    const float* h1_b2 = (const float*)d_in[19];
    const float* h1_g  = (const float*)d_in[20];
    const float* h1_be = (const float*)d_in[21];
    float* out = (float*)d_out;

    const int* src = ei;
    const int* dst = ei + EE;

    float *pz, *pbsum, *pbsq, *pbcat, *pbcat2;
    uint32_t *pWF, *paggH, *paggL;
    cudaGetSymbolAddress((void**)&pz, d_z);
    cudaGetSymbolAddress((void**)&pbsum, d_bsumL);
    cudaGetSymbolAddress((void**)&pbsq, d_bsqL);
    cudaGetSymbolAddress((void**)&pbcat, d_bcat);
    cudaGetSymbolAddress((void**)&pbcat2, d_bcat2);
    cudaGetSymbolAddress((void**)&pWF, d_WF32);
    cudaGetSymbolAddress((void**)&paggH, d_aggH);
    cudaGetSymbolAddress((void**)&paggL, d_aggL);

    cudaFuncSetAttribute(fgemm_kernel, cudaFuncAttributeMaxDynamicSharedMemorySize, SM_G);

    const int grid_nf   = (NN * 32 + 255) / 256;
    const int grid_cv   = (NN * 16 + 255) / 256;
    const int grid_e    = (EE + 255) / 256;
    const int grid_gemm = (NN + 127) / 128;
    const int grid_bd   = (NN + 127) / 128;

    zero_deg_kernel<<<NB, 256>>>();
    prep0_kernel<<<grid_e, 256>>>(gc_W1, gc_W2, h0_W1, h0_b1, h0_W2, h0_b2,
                                  x, dst, batch, out);
    scan1_kernel<<<NB, 256>>>();
    scan23_kernel<<<NB, 256>>>();
    fill_kernel<<<grid_e, 256>>>(src, dst);

    gather_kernel<<<grid_nf, 256>>>();

    for (int i = 0; i < 4; i++) {
        const uint32_t* w1f = pWF + (2 * i) * 16384;
        const uint32_t* w2f = pWF + (2 * i + 1) * 16384;
        const float* bb1 = (i < 3) ? (gc_b1 + i * FF) : pbcat;
        const float* bb2 = (i < 3) ? (gc_b2 + i * FF) : pbcat2;
        const float* gg  = (i < 3) ? (gc_g + i * FF) : h0_g;
        const float* bbe = (i < 3) ? (gc_be + i * FF) : h0_be;
        int relu = (i == 2) ? 0 : 1;
        fgemm_kernel<<<grid_gemm, 256, SM_G>>>(paggH, paggL,
            w1f, bb1, w2f, bb2,
            pz, pbsum + i * FF, pbsq + i * FF, NN);
        bnh_kernel<<<grid_cv, 256>>>(pz, gg, bbe, pbsum + i * FF, pbsq + i * FF, relu);
        gather_kernel<<<grid_nf, 256>>>();
    }

    bdiag2_pool_kernel<<<grid_bd, 256>>>(paggH, paggL, h1_W1, h1_b1, h1_W2, h1_b2,
                                         batch, out, pbsum + 4 * FF, pbsq + 4 * FF);

    finalize_kernel<<<(GG * FF + 255) / 256, 256>>>(out, h1_g, h1_be,
                                                    pbsum + 4 * FF, pbsq + 4 * FF);
}

// round 17
// speedup vs baseline: 1.0502x; 1.0502x over previous
#include <cuda_runtime.h>
#include <cuda_fp16.h>
#include <cstdint>

#define NN 50000
#define EE 800000
#define FF 128
#define KK 8
#define DD 16
#define GG 512
#define GC 3
#define BN_EPS 1e-5f
#define NB 196   // ceil(NN/256)

// ---------------- static scratch ----------------
__device__ float    d_z[NN * FF];
__device__ __half   d_hh[NN * FF];     // fp16 bn(z) for gather
__device__ uint32_t d_aggH[NN * 64];   // packed bf16-hi pairs of agg
__device__ uint32_t d_aggL[NN * 64];
__device__ uint32_t d_WF32[8 * 16384]; // interleaved frags: {H0,H1,L0,L1} per (n,ks,j)
__device__ int      d_deg[NN];
__device__ int      d_rowptr[NN];
__device__ int      d_cur[NN];
__device__ int      d_esrc[EE];
__device__ int      d_bsumblk[256];
__device__ int      d_gcnt[GG];
__device__ float    d_bsumL[5 * FF];
__device__ float    d_bsqL[5 * FF];
__device__ float    d_bcat[FF];
__device__ float    d_bcat2[FF];

// ================= helpers =================
__device__ __forceinline__ uint32_t smem_u32(const void* p) {
    uint32_t a;
    asm("{ .reg .u64 t; cvta.to.shared.u64 t, %1; cvt.u32.u64 %0, t; }" : "=r"(a) : "l"(p));
    return a;
}
__device__ __forceinline__ uint32_t h2_to_u(__half2 h) {
    return *reinterpret_cast<uint32_t*>(&h);
}
__device__ __forceinline__ float2 u_to_f2(uint32_t u) {
    __half2 h = *reinterpret_cast<__half2*>(&u);
    return __half22float2(h);
}
__device__ __forceinline__ void split1(float v, uint32_t& h, uint32_t& l) {
    uint32_t u = __float_as_uint(v);
    uint32_t hr = (u + 0x7FFFu + ((u >> 16) & 1u)) & 0xFFFF0000u;
    float hf = __uint_as_float(hr);
    float lf = v - hf;
    uint32_t ul = __float_as_uint(lf);
    h = hr >> 16;
    l = (ul + 0x7FFFu + ((ul >> 16) & 1u)) >> 16;
}
__device__ __forceinline__ void unpack2(uint32_t h, uint32_t l, float& a, float& b) {
    a = __uint_as_float((h & 0xFFFFu) << 16) + __uint_as_float((l & 0xFFFFu) << 16);
    b = __uint_as_float(h & 0xFFFF0000u) + __uint_as_float(l & 0xFFFF0000u);
}
__device__ __forceinline__ void ldsm4(uint32_t* r, uint32_t addr) {
    asm volatile("ldmatrix.sync.aligned.m8n8.x4.shared.b16 {%0,%1,%2,%3}, [%4];"
                 : "=r"(r[0]), "=r"(r[1]), "=r"(r[2]), "=r"(r[3]) : "r"(addr));
}
__device__ __forceinline__ void mma_bf16(float* c, const uint32_t* a, const uint32_t* b) {
    asm volatile(
        "mma.sync.aligned.m16n8k16.row.col.f32.bf16.bf16.f32 "
        "{%0,%1,%2,%3}, {%4,%5,%6,%7}, {%8,%9}, {%0,%1,%2,%3};"
        : "+f"(c[0]), "+f"(c[1]), "+f"(c[2]), "+f"(c[3])
        : "r"(a[0]), "r"(a[1]), "r"(a[2]), "r"(a[3]), "r"(b[0]), "r"(b[1]));
}
__device__ __forceinline__ void add8(float* acc, uint4 v) {
    float2 p0 = u_to_f2(v.x), p1 = u_to_f2(v.y), p2 = u_to_f2(v.z), p3 = u_to_f2(v.w);
    acc[0] += p0.x; acc[1] += p0.y; acc[2] += p1.x; acc[3] += p1.y;
    acc[4] += p2.x; acc[5] += p2.y; acc[6] += p3.x; acc[7] += p3.y;
}

#define RSTRIDE 272
#define O_AH 0
#define O_AL 34816
#define SM_G 69632

// ---------------- prep0: zero + weights + hist + x->fp16, all independent ----------------
__global__ void __launch_bounds__(256) prep0_kernel(const float* __restrict__ gc_W1,
                                                    const float* __restrict__ gc_W2,
                                                    const float* __restrict__ h0_W1,
                                                    const float* __restrict__ h0_b1,
                                                    const float* __restrict__ h0_W2,
                                                    const float* __restrict__ h0_b2,
                                                    const float* __restrict__ x,
                                                    const int* __restrict__ dst,
                                                    const int* __restrict__ batch,
                                                    float* __restrict__ out) {
    int idx = blockIdx.x * 256 + threadIdx.x;   // 800000 threads

    if (idx < EE) atomicAdd(&d_deg[dst[idx]], 1);
    if (idx < NN) atomicAdd(&d_gcnt[batch[idx]], 1);

    if (idx < GG * FF) out[idx] = 0.f;
    if (idx < 5 * FF) { d_bsumL[idx] = 0.f; d_bsqL[idx] = 0.f; }
    if (idx < FF) {
        d_bcat[idx]  = h0_b1[(idx >> 4) * DD + (idx & 15)];
        d_bcat2[idx] = h0_b2[(idx >> 4) * DD + (idx & 15)];
    }

    if (idx < 8 * 8192) {
        int s = idx >> 13, o = idx & 8191;
        int which = o & 1, j = (o >> 1) & 3, ks = (o >> 3) & 7, n = o >> 6;
        int kp = ks * 8 + j + which * 4;
        int k0 = kp * 2, k1 = k0 + 1;
        float w0, w1;
        if (s < 6) {
            const float* W = ((s & 1) ? gc_W2 : gc_W1) + (s >> 1) * 16384;
            w0 = W[k0 * 128 + n];
            w1 = W[k1 * 128 + n];
        } else if (s == 6) {
            w0 = h0_W1[(n >> 4) * (FF * DD) + k0 * DD + (n & 15)];
            w1 = h0_W1[(n >> 4) * (FF * DD) + k1 * DD + (n & 15)];
        } else {
            int kb = n >> 4;
            w0 = ((k0 >> 4) == kb) ? h0_W2[kb * (DD * DD) + (k0 & 15) * DD + (n & 15)] : 0.f;
            w1 = ((k1 >> 4) == kb) ? h0_W2[kb * (DD * DD) + (k1 & 15) * DD + (n & 15)] : 0.f;
        }
        uint32_t h0v, l0, h1v, l1;
        split1(w0, h0v, l0); split1(w1, h1v, l1);
        int q = o >> 1;
        d_WF32[s * 16384 + q * 4 + which]     = h0v | (h1v << 16);
        d_WF32[s * 16384 + q * 4 + 2 + which] = l0 | (l1 << 16);
    }

    if (idx < NN * 16) {
        int f8 = (idx & 15) << 3;
        const float4* zp = (const float4*)(x + ((size_t)(idx >> 4) << 7) + f8);
        float4 v0 = zp[0], v1 = zp[1];
        uint4 o2;
        o2.x = h2_to_u(__floats2half2_rn(v0.x, v0.y));
        o2.y = h2_to_u(__floats2half2_rn(v0.z, v0.w));
        o2.z = h2_to_u(__floats2half2_rn(v1.x, v1.y));
        o2.w = h2_to_u(__floats2half2_rn(v1.z, v1.w));
        *(uint4*)(d_hh + ((size_t)(idx >> 4) << 7) + f8) = o2;
    }
}

__global__ void zero_deg_kernel() {
    int n = blockIdx.x * 256 + threadIdx.x;
    if (n < NN) d_deg[n] = 0;
    if (n < GG) d_gcnt[n] = 0;
}

__global__ void scan1_kernel() {
    __shared__ int s[256];
    int n = blockIdx.x * 256 + threadIdx.x;
    s[threadIdx.x] = (n < NN) ? d_deg[n] : 0;
    __syncthreads();
    for (int o = 128; o > 0; o >>= 1) {
        if (threadIdx.x < o) s[threadIdx.x] += s[threadIdx.x + o];
        __syncthreads();
    }
    if (threadIdx.x == 0) d_bsumblk[blockIdx.x] = s[0];
}
__global__ void scan23_kernel() {
    __shared__ int sb[256];
    __shared__ int s[256];
    int tid = threadIdx.x;
    int bv = (tid < NB) ? d_bsumblk[tid] : 0;
    sb[tid] = bv;
    __syncthreads();
    for (int o = 1; o < 256; o <<= 1) {
        int t = (tid >= o) ? sb[tid - o] : 0;
        __syncthreads();
        sb[tid] += t;
        __syncthreads();
    }
    int block_off = sb[blockIdx.x] - ((blockIdx.x < NB) ? d_bsumblk[blockIdx.x] : 0);
    __syncthreads();
    int n = blockIdx.x * 256 + tid;
    int v = (n < NN) ? d_deg[n] : 0;
    s[tid] = v;
    __syncthreads();
    for (int o = 1; o < 256; o <<= 1) {
        int t = (tid >= o) ? s[tid - o] : 0;
        __syncthreads();
        s[tid] += t;
        __syncthreads();
    }
    if (n < NN) {
        int rp = block_off + s[tid] - v;
        d_rowptr[n] = rp;
        d_cur[n] = rp;
    }
}
__global__ void fill_kernel(const int* __restrict__ src, const int* __restrict__ dst) {
    int e = blockIdx.x * 256 + threadIdx.x;
    if (e >= EE) return;
    int pos = atomicAdd(&d_cur[dst[e]], 1);
    d_esrc[pos] = src[e];
}

// ---------------- bnh: d_hh = half(bn(z)(+relu)) ----------------
__global__ void __launch_bounds__(256) bnh_kernel(const float* __restrict__ z,
                                                  const float* __restrict__ g,
                                                  const float* __restrict__ be,
                                                  const float* __restrict__ bsum,
                                                  const float* __restrict__ bsq,
                                                  int relu) {
    __shared__ float ssc[FF], ssh[FF];
    int tid = threadIdx.x;
    if (tid < FF) {
        float mu  = bsum[tid] * (1.0f / NN);
        float var = bsq[tid]  * (1.0f / NN) - mu * mu;
        float sc  = g[tid] * rsqrtf(var + BN_EPS);
        ssc[tid] = sc;
        ssh[tid] = be[tid] - mu * sc;
    }
    __syncthreads();
    int idx = blockIdx.x * 256 + tid;
    if (idx >= NN * 16) return;
    int f8 = (idx & 15) << 3;
    const float4* zp = (const float4*)(z + ((size_t)(idx >> 4) << 7) + f8);
    float4 v0 = zp[0], v1 = zp[1];
    float4 sc0 = *(const float4*)&ssc[f8], sh0 = *(const float4*)&ssh[f8];
    float4 sc1 = *(const float4*)&ssc[f8 + 4], sh1 = *(const float4*)&ssh[f8 + 4];
    v0.x = v0.x * sc0.x + sh0.x; v0.y = v0.y * sc0.y + sh0.y;
    v0.z = v0.z * sc0.z + sh0.z; v0.w = v0.w * sc0.w + sh0.w;
    v1.x = v1.x * sc1.x + sh1.x; v1.y = v1.y * sc1.y + sh1.y;
    v1.z = v1.z * sc1.z + sh1.z; v1.w = v1.w * sc1.w + sh1.w;
    if (relu) {
        v0.x = fmaxf(v0.x, 0.f); v0.y = fmaxf(v0.y, 0.f);
        v0.z = fmaxf(v0.z, 0.f); v0.w = fmaxf(v0.w, 0.f);
        v1.x = fmaxf(v1.x, 0.f); v1.y = fmaxf(v1.y, 0.f);
        v1.w = fmaxf(v1.w, 0.f); v1.z = fmaxf(v1.z, 0.f);
    }
    uint4 o;
    o.x = h2_to_u(__floats2half2_rn(v0.x, v0.y));
    o.y = h2_to_u(__floats2half2_rn(v0.z, v0.w));
    o.z = h2_to_u(__floats2half2_rn(v1.x, v1.y));
    o.w = h2_to_u(__floats2half2_rn(v1.z, v1.w));
    *(uint4*)(d_hh + ((size_t)(idx >> 4) << 7) + f8) = o;
}

// ---------------- gather: warp/node, 4 edges in flight per lane-half ----------------
__global__ void __launch_bounds__(256) gather_kernel() {
    int gt = blockIdx.x * 256 + threadIdx.x;
    int w = gt >> 5, lane = gt & 31;
    if (w >= NN) return;
    int half = lane >> 4;
    int fo = (lane & 15) << 3;
    int start = d_rowptr[w];
    int deg = d_deg[w];

    float acc[8];
#pragma unroll
    for (int j = 0; j < 8; j++) acc[j] = 0.f;

    if (half == 0)
        add8(acc, *(const uint4*)(d_hh + ((size_t)w << 7) + fo));

    int i = half;
    for (; i + 6 < deg; i += 8) {
        int s0 = d_esrc[start + i];
        int s1 = d_esrc[start + i + 2];
        int s2 = d_esrc[start + i + 4];
        int s3 = d_esrc[start + i + 6];
        uint4 v0 = *(const uint4*)(d_hh + ((size_t)s0 << 7) + fo);
        uint4 v1 = *(const uint4*)(d_hh + ((size_t)s1 << 7) + fo);
        uint4 v2 = *(const uint4*)(d_hh + ((size_t)s2 << 7) + fo);
        uint4 v3 = *(const uint4*)(d_hh + ((size_t)s3 << 7) + fo);
        add8(acc, v0);
        add8(acc, v1);
        add8(acc, v2);
        add8(acc, v3);
    }
    for (; i < deg; i += 2) {
        int s0 = d_esrc[start + i];
        add8(acc, *(const uint4*)(d_hh + ((size_t)s0 << 7) + fo));
    }

#pragma unroll
    for (int j = 0; j < 8; j++)
        acc[j] += __shfl_xor_sync(0xFFFFFFFFu, acc[j], 16);

    if (half == 0) {
        uint32_t ph[4], pl[4];
#pragma unroll
        for (int j = 0; j < 4; j++) {
            uint32_t h0, l0, h1, l1;
            split1(acc[2 * j], h0, l0);
            split1(acc[2 * j + 1], h1, l1);
            ph[j] = h0 | (h1 << 16);
            pl[j] = l0 | (l1 << 16);
        }
        size_t base = (size_t)w * 64 + ((lane & 15) << 2);
        *(uint4*)&d_aggH[base] = make_uint4(ph[0], ph[1], ph[2], ph[3]);
        *(uint4*)&d_aggL[base] = make_uint4(pl[0], pl[1], pl[2], pl[3]);
    }
}

// ---------------- fused double GEMM, 1m x 8n warp layout (no W duplication) ----------------
// Each warp: 16 N-cols (nw = wid*16), all 128 M-rows (mt 0..7). c[8][2][4].
__global__ void __launch_bounds__(256, 2) fgemm_kernel(const uint32_t* __restrict__ AH,
                                                       const uint32_t* __restrict__ AL,
                                                       const uint32_t* __restrict__ W1F,
                                                       const float* __restrict__ b1,
                                                       const uint32_t* __restrict__ W2F,
                                                       const float* __restrict__ b2,
                                                       float* __restrict__ Cz,
                                                       float* __restrict__ bsum,
                                                       float* __restrict__ bsq,
                                                       int M) {
    extern __shared__ char sm[];
    uint32_t sb = smem_u32(sm);
    const int tid = threadIdx.x;
    const int row0 = blockIdx.x * 128;

    for (int i = tid; i < 2048; i += 256) {
        int m = i >> 4, c4 = (i & 15) << 2;
        int r = row0 + m; if (r >= M) r = M - 1;
        uint32_t off = (uint32_t)m * RSTRIDE + (c4 << 2);
        *(uint4*)(sm + O_AH + off) = *(const uint4*)&AH[(size_t)r * 64 + c4];
        *(uint4*)(sm + O_AL + off) = *(const uint4*)&AL[(size_t)r * 64 + c4];
    }
    __syncthreads();

    const int wid = tid >> 5, lane = tid & 31;
    const int nw = wid << 4;                  // 16 cols per warp
    const int lane15 = lane & 15, lhi = lane >> 4;
    const int rr = lane >> 2, cc = (lane & 3) << 1;

    uint32_t baseA = sb + O_AH + (uint32_t)lane15 * RSTRIDE + (lhi << 4);
    // fi4 = n*128 + ks*16 + j*4 ; n = nw + nt*8 + (lane>>2), j = lane&3
    const uint32_t fb4 = (uint32_t)(nw + (lane >> 2)) * 128 + ((lane & 3) << 2);

    float c[8][2][4];

#define MMA_PHASE(WF_)                                                           \
    for (int ks = 0; ks < 8; ks++) {                                             \
        uint32_t bh[2][2], bl[2][2];                                             \
        _Pragma("unroll")                                                        \
        for (int nt = 0; nt < 2; nt++) {                                         \
            uint32_t fi4 = fb4 + (uint32_t)nt * 1024 + (uint32_t)ks * 16;        \
            uint4 vf = *(const uint4*)&WF_[fi4];                                 \
            bh[nt][0] = vf.x; bh[nt][1] = vf.y;                                  \
            bl[nt][0] = vf.z; bl[nt][1] = vf.w;                                  \
        }                                                                        \
        _Pragma("unroll")                                                        \
        for (int mt = 0; mt < 8; mt++) {                                         \
            uint32_t ah[4], al[4];                                               \
            uint32_t ad = baseA + mt * (16 * RSTRIDE) + ks * 32;                 \
            ldsm4(ah, ad);                                                       \
            ldsm4(al, ad + (O_AL - O_AH));                                       \
            _Pragma("unroll")                                                    \
            for (int nt = 0; nt < 2; nt++) {                                     \
                mma_bf16(c[mt][nt], ah, bh[nt]);                                 \
                mma_bf16(c[mt][nt], ah, bl[nt]);                                 \
                mma_bf16(c[mt][nt], al, bh[nt]);                                 \
            }                                                                    \
        }                                                                        \
    }

    // ---- phase 1: t = relu(A@W1 + b1) ----
#pragma unroll
    for (int a = 0; a < 8; a++)
#pragma unroll
        for (int b = 0; b < 2; b++)
#pragma unroll
            for (int d = 0; d < 4; d++) c[a][b][d] = 0.f;
    MMA_PHASE(W1F);
    __syncthreads();

#pragma unroll
    for (int mt = 0; mt < 8; mt++) {
        int mr0 = mt * 16 + rr;
        int mr1 = mr0 + 8;
#pragma unroll
        for (int nt = 0; nt < 2; nt++) {
            int gc = nw + nt * 8 + cc;
            float bx = b1[gc], by = b1[gc + 1];
            float v0 = fmaxf(c[mt][nt][0] + bx, 0.f);
            float v1 = fmaxf(c[mt][nt][1] + by, 0.f);
            float v2 = fmaxf(c[mt][nt][2] + bx, 0.f);
            float v3 = fmaxf(c[mt][nt][3] + by, 0.f);
            uint32_t h0, l0, h1, l1, h2, l2, h3, l3;
            split1(v0, h0, l0); split1(v1, h1, l1);
            split1(v2, h2, l2); split1(v3, h3, l3);
            uint32_t off0 = (uint32_t)mr0 * RSTRIDE + ((gc >> 1) << 2);
            uint32_t off1 = (uint32_t)mr1 * RSTRIDE + ((gc >> 1) << 2);
            *(uint32_t*)(sm + O_AH + off0) = h0 | (h1 << 16);
            *(uint32_t*)(sm + O_AL + off0) = l0 | (l1 << 16);
            *(uint32_t*)(sm + O_AH + off1) = h2 | (h3 << 16);
            *(uint32_t*)(sm + O_AL + off1) = l2 | (l3 << 16);
        }
    }
    __syncthreads();

    // ---- phase 2: z = t@W2 + b2 ----
#pragma unroll
    for (int a = 0; a < 8; a++)
#pragma unroll
        for (int b = 0; b < 2; b++)
#pragma unroll
            for (int d = 0; d < 4; d++) c[a][b][d] = 0.f;
    MMA_PHASE(W2F);

    float s[2][2], q[2][2];
#pragma unroll
    for (int nt = 0; nt < 2; nt++) { s[nt][0] = s[nt][1] = q[nt][0] = q[nt][1] = 0.f; }
#pragma unroll
    for (int mt = 0; mt < 8; mt++) {
        int gr0 = row0 + mt * 16 + rr;
        int gr1 = gr0 + 8;
#pragma unroll
        for (int nt = 0; nt < 2; nt++) {
            int gc = nw + nt * 8 + cc;
            float bx = b2[gc], by = b2[gc + 1];
            float v0 = c[mt][nt][0] + bx, v1 = c[mt][nt][1] + by;
            float v2 = c[mt][nt][2] + bx, v3 = c[mt][nt][3] + by;
            if (gr0 < M) {
                *(float2*)(Cz + (size_t)gr0 * FF + gc) = make_float2(v0, v1);
                s[nt][0] += v0; q[nt][0] += v0 * v0; s[nt][1] += v1; q[nt][1] += v1 * v1;
            }
            if (gr1 < M) {
                *(float2*)(Cz + (size_t)gr1 * FF + gc) = make_float2(v2, v3);
                s[nt][0] += v2; q[nt][0] += v2 * v2; s[nt][1] += v3; q[nt][1] += v3 * v3;
            }
        }
    }
#pragma unroll
    for (int off = 16; off >= 4; off >>= 1) {
#pragma unroll
        for (int nt = 0; nt < 2; nt++) {
#pragma unroll
            for (int j = 0; j < 2; j++) {
                s[nt][j] += __shfl_xor_sync(0xFFFFFFFFu, s[nt][j], off);
                q[nt][j] += __shfl_xor_sync(0xFFFFFFFFu, q[nt][j], off);
            }
        }
    }
    if (lane < 4) {
#pragma unroll
        for (int nt = 0; nt < 2; nt++) {
            int gc = nw + nt * 8 + (lane << 1);
            atomicAdd(&bsum[gc], s[nt][0]);
            atomicAdd(&bsum[gc + 1], s[nt][1]);
            atomicAdd(&bsq[gc], q[nt][0]);
            atomicAdd(&bsq[gc + 1], q[nt][1]);
        }
    }
#undef MMA_PHASE
}

// ---------------- block-diag double + fused stats + direct raw pooling ----------------
__global__ void __launch_bounds__(256) bdiag2_pool_kernel(const uint32_t* __restrict__ XH,
                                                          const uint32_t* __restrict__ XL,
                                                          const float* __restrict__ W1,
                                                          const float* __restrict__ B1,
                                                          const float* __restrict__ W2,
                                                          const float* __restrict__ B2,
                                                          const int* __restrict__ batch,
                                                          float* __restrict__ out,
                                                          float* __restrict__ bsum,
                                                          float* __restrict__ bsq) {
    __shared__ float sW1[8 * 257];
    __shared__ float sW2[8 * 257];
    __shared__ float sB1[128];
    __shared__ float sB2[128];
    __shared__ float sSum[128], sSq[128];
    int tid = threadIdx.x;
    for (int i = tid; i < 2048; i += 256) {
        sW1[(i >> 8) * 257 + (i & 255)] = W1[i];
        sW2[(i >> 8) * 257 + (i & 255)] = W2[i];
    }
    if (tid < 128) { sB1[tid] = B1[tid]; sB2[tid] = B2[tid]; sSum[tid] = 0.f; sSq[tid] = 0.f; }
    __syncthreads();
    int k = tid & 7;
    const float* w1 = sW1 + k * 257;
    const float* w2 = sW2 + k * 257;
    float s[16], q[16];
#pragma unroll
    for (int j = 0; j < 16; j++) { s[j] = 0.f; q[j] = 0.f; }

    for (int it = 0; it < 4; it++) {
        int n = blockIdx.x * 128 + it * 32 + (tid >> 3);
        if (n >= NN) break;
        size_t base = (size_t)n * 64 + k * 8;
        uint4 vh0 = *(const uint4*)&XH[base];
        uint4 vh1 = *(const uint4*)&XH[base + 4];
        uint4 vl0 = *(const uint4*)&XL[base];
        uint4 vl1 = *(const uint4*)&XL[base + 4];
        float x[16];
        unpack2(vh0.x, vl0.x, x[0], x[1]);   unpack2(vh0.y, vl0.y, x[2], x[3]);
        unpack2(vh0.z, vl0.z, x[4], x[5]);   unpack2(vh0.w, vl0.w, x[6], x[7]);
        unpack2(vh1.x, vl1.x, x[8], x[9]);   unpack2(vh1.y, vl1.y, x[10], x[11]);
        unpack2(vh1.z, vl1.z, x[12], x[13]); unpack2(vh1.w, vl1.w, x[14], x[15]);
        float t[16];
#pragma unroll
        for (int j = 0; j < 16; j++) t[j] = sB1[k * 16 + j];
#pragma unroll
        for (int i2 = 0; i2 < 16; i2++) {
            float xi = x[i2];
#pragma unroll
            for (int j = 0; j < 16; j++) t[j] += xi * w1[i2 * 16 + j];
        }
#pragma unroll
        for (int j = 0; j < 16; j++) t[j] = fmaxf(t[j], 0.f);
        float o[16];
#pragma unroll
        for (int j = 0; j < 16; j++) o[j] = sB2[k * 16 + j];
#pragma unroll
        for (int i2 = 0; i2 < 16; i2++) {
            float ti = t[i2];
#pragma unroll
            for (int j = 0; j < 16; j++) o[j] += ti * w2[i2 * 16 + j];
        }
        int g = batch[n];
        float* op = out + (size_t)g * FF + k * DD;
#pragma unroll
        for (int i2 = 0; i2 < 4; i2++) {
            asm volatile("red.global.add.v4.f32 [%0], {%1,%2,%3,%4};"
                         :: "l"(op + 4 * i2), "f"(o[4*i2]), "f"(o[4*i2+1]),
                            "f"(o[4*i2+2]), "f"(o[4*i2+3]) : "memory");
        }
#pragma unroll
        for (int j = 0; j < 16; j++) { s[j] += o[j]; q[j] += o[j] * o[j]; }
    }
#pragma unroll
    for (int off = 16; off >= 8; off >>= 1) {
#pragma unroll
        for (int j = 0; j < 16; j++) {
            s[j] += __shfl_xor_sync(0xFFFFFFFFu, s[j], off);
            q[j] += __shfl_xor_sync(0xFFFFFFFFu, q[j], off);
        }
    }
    if ((tid & 31) < 8) {
#pragma unroll
        for (int j = 0; j < 16; j++) {
            atomicAdd(&sSum[k * 16 + j], s[j]);
            atomicAdd(&sSq[k * 16 + j], q[j]);
        }
    }
    __syncthreads();
    if (tid < 128) {
        atomicAdd(&bsum[tid], sSum[tid]);
        atomicAdd(&bsq[tid], sSq[tid]);
    }
}

// ---------------- finalize: out = out*sc + cnt_g*sh ----------------
__global__ void __launch_bounds__(256) finalize_kernel(float* __restrict__ out,
                                                       const float* __restrict__ g,
                                                       const float* __restrict__ be,
                                                       const float* __restrict__ bsum,
                                                       const float* __restrict__ bsq) {
    int idx = blockIdx.x * 256 + threadIdx.x;
    if (idx >= GG * FF) return;
    int f = idx & 127;
    int gi = idx >> 7;
    float mu  = bsum[f] * (1.0f / NN);
    float var = bsq[f]  * (1.0f / NN) - mu * mu;
    float sc  = g[f] * rsqrtf(var + BN_EPS);
    float sh  = be[f] - mu * sc;
    out[idx] = out[idx] * sc + (float)d_gcnt[gi] * sh;
}

// ---------------- host orchestration ----------------
extern "C" void kernel_launch(void* const* d_in, const int* in_sizes, int n_in,
                              void* d_out, int out_size) {
    const float* x     = (const float*)d_in[0];
    const int*   ei    = (const int*)d_in[1];
    const int*   batch = (const int*)d_in[2];
    const float* gc_W1 = (const float*)d_in[4];
    const float* gc_b1 = (const float*)d_in[5];
    const float* gc_W2 = (const float*)d_in[6];
    const float* gc_b2 = (const float*)d_in[7];
    const float* gc_g  = (const float*)d_in[8];
    const float* gc_be = (const float*)d_in[9];
    const float* h0_W1 = (const float*)d_in[10];
    const float* h0_b1 = (const float*)d_in[11];
    const float* h0_W2 = (const float*)d_in[12];
    const float* h0_b2 = (const float*)d_in[13];
    const float* h0_g  = (const float*)d_in[14];
    const float* h0_be = (const float*)d_in[15];
    const float* h1_W1 = (const float*)d_in[16];
    const float* h1_b1 = (const float*)d_in[17];
    const float* h1_W2 = (const float*)d_in[18];
    const float* h1_b2 = (const float*)d_in[19];
    const float* h1_g  = (const float*)d_in[20];
    const float* h1_be = (const float*)d_in[21];
    float* out = (float*)d_out;

    const int* src = ei;
    const int* dst = ei + EE;

    float *pz, *pbsum, *pbsq, *pbcat, *pbcat2;
    uint32_t *pWF, *paggH, *paggL;
    cudaGetSymbolAddress((void**)&pz, d_z);
    cudaGetSymbolAddress((void**)&pbsum, d_bsumL);
    cudaGetSymbolAddress((void**)&pbsq, d_bsqL);
    cudaGetSymbolAddress((void**)&pbcat, d_bcat);
    cudaGetSymbolAddress((void**)&pbcat2, d_bcat2);
    cudaGetSymbolAddress((void**)&pWF, d_WF32);
    cudaGetSymbolAddress((void**)&paggH, d_aggH);
    cudaGetSymbolAddress((void**)&paggL, d_aggL);

    cudaFuncSetAttribute(fgemm_kernel, cudaFuncAttributeMaxDynamicSharedMemorySize, SM_G);

    const int grid_nf   = (NN * 32 + 255) / 256;
    const int grid_cv   = (NN * 16 + 255) / 256;
    const int grid_e    = (EE + 255) / 256;
    const int grid_gemm = (NN + 127) / 128;
    const int grid_bd   = (NN + 127) / 128;

    zero_deg_kernel<<<NB, 256>>>();
    prep0_kernel<<<grid_e, 256>>>(gc_W1, gc_W2, h0_W1, h0_b1, h0_W2, h0_b2,
                                  x, dst, batch, out);
    scan1_kernel<<<NB, 256>>>();
    scan23_kernel<<<NB, 256>>>();
    fill_kernel<<<grid_e, 256>>>(src, dst);

    gather_kernel<<<grid_nf, 256>>>();

    for (int i = 0; i < 4; i++) {
        const uint32_t* w1f = pWF + (2 * i) * 16384;
        const uint32_t* w2f = pWF + (2 * i + 1) * 16384;
        const float* bb1 = (i < 3) ? (gc_b1 + i * FF) : pbcat;
        const float* bb2 = (i < 3) ? (gc_b2 + i * FF) : pbcat2;
        const float* gg  = (i < 3) ? (gc_g + i * FF) : h0_g;
        const float* bbe = (i < 3) ? (gc_be + i * FF) : h0_be;
        int relu = (i == 2) ? 0 : 1;
        fgemm_kernel<<<grid_gemm, 256, SM_G>>>(paggH, paggL,
            w1f, bb1, w2f, bb2,
            pz, pbsum + i * FF, pbsq + i * FF, NN);
        bnh_kernel<<<grid_cv, 256>>>(pz, gg, bbe, pbsum + i * FF, pbsq + i * FF, relu);
        gather_kernel<<<grid_nf, 256>>>();
    }

    bdiag2_pool_kernel<<<grid_bd, 256>>>(paggH, paggL, h1_W1, h1_b1, h1_W2, h1_b2,
                                         batch, out, pbsum + 4 * FF, pbsq + 4 * FF);

    finalize_kernel<<<(GG * FF + 255) / 256, 256>>>(out, h1_g, h1_be,
                                                    pbsum + 4 * FF, pbsq + 4 * FF);
}